// round 10
// baseline (speedup 1.0000x reference)
#include <cuda_runtime.h>
#include <math.h>

#define NGENES 512
#define NBF 128                         /* fine bins */
#define HTOT (NGENES * NBF)             /* 65536 */
#define REPL 4                          /* histogram replicas */
#define MAXFRAG 2100000

// L2-resident scratch (no allocations allowed -> __device__ globals).
// g_hist is zero-initialized at module load and RE-ZEROED by mlp_softmax_kernel
// after reading, so every graph replay starts from a clean histogram.
__device__ int            g_hist[REPL][HTOT];
__device__ float          g_comb[HTOT];       // cconst + L0+L1+L2 combined logits
__device__ unsigned short g_fkey[MAXFRAG];    // per-fragment packed key g*128+bin

// Exact integer reproduction of jnp.searchsorted(interior_bins, x, side='left')
// for equal-width bins: idx = ceil(x*nb/20000) - 1, clamped at 0 via trunc division.
__device__ __forceinline__ int bin_idx128(int x) {
    return (x * NBF - 1) / 20000;
}

// Fused kernel: "key blocks" (2-of-7) precompute packed fragment keys;
// "hist blocks" (5-of-7) count motifs. Atomics are LANE-SERIALIZED: each
// RED instruction has exactly ONE active lane -> one L1tex wavefront per
// instruction, pipelining at 1.0 cyc/wf instead of 2.07 cyc/wf replay rate
// of a 32-lane spread RED.
__global__ void hist_and_key_kernel(const int* __restrict__ mpos,
                                    const int* __restrict__ mgene, int nmot,
                                    const int* __restrict__ coords,
                                    const int* __restrict__ fgene, int nfrag) {
    int b  = blockIdx.x;
    int r7 = b % 7, q = b / 7;

    if (r7 < 2) {
        // ---- fragment key block (2048 fragments) ----
        int kb = q * 2 + r7;
        int i  = kb * 2048 + threadIdx.x * 8;
        if (i + 7 < nfrag) {
            int4 x0 = *reinterpret_cast<const int4*>(coords + i);
            int4 x1 = *reinterpret_cast<const int4*>(coords + i + 4);
            int4 g0 = *reinterpret_cast<const int4*>(fgene + i);
            int4 g1 = *reinterpret_cast<const int4*>(fgene + i + 4);
            uint4 pk;
            pk.x = (unsigned)(g0.x * NBF + bin_idx128(x0.x))
                 | ((unsigned)(g0.y * NBF + bin_idx128(x0.y)) << 16);
            pk.y = (unsigned)(g0.z * NBF + bin_idx128(x0.z))
                 | ((unsigned)(g0.w * NBF + bin_idx128(x0.w)) << 16);
            pk.z = (unsigned)(g1.x * NBF + bin_idx128(x1.x))
                 | ((unsigned)(g1.y * NBF + bin_idx128(x1.y)) << 16);
            pk.w = (unsigned)(g1.z * NBF + bin_idx128(x1.z))
                 | ((unsigned)(g1.w * NBF + bin_idx128(x1.w)) << 16);
            *reinterpret_cast<uint4*>(g_fkey + i) = pk;
        } else if (i < nfrag) {
            for (; i < nfrag; i++)
                g_fkey[i] = (unsigned short)(fgene[i] * NBF + bin_idx128(coords[i]));
        }
    } else {
        // ---- histogram block (2048 motifs, lane-serialized REDs) ----
        int hb   = q * 5 + (r7 - 2);
        int base = hb * 2048;
        int lane = threadIdx.x & 31;
        int warp = threadIdx.x >> 5;     // 0..7
        int* __restrict__ hist = g_hist[b & 3];

        // warp handles 256 motifs: 8 batches of 32 (one motif per lane)
#pragma unroll
        for (int bt = 0; bt < 8; bt++) {
            int idx = base + warp * 256 + bt * 32 + lane;
            int key = -1;
            if (idx < nmot)
                key = mgene[idx] * NBF + bin_idx128(mpos[idx]);
            // one RED instruction per active lane: 1 wavefront each,
            // cross-instruction pipelining at ~1 cyc/wf
#pragma unroll
            for (int j = 0; j < 32; j++) {
                if (lane == j && key >= 0)
                    atomicAdd(&hist[key], 1);
            }
        }
    }
}

__device__ __forceinline__ float wmax(float v) {
#pragma unroll
    for (int s = 16; s > 0; s >>= 1) v = fmaxf(v, __shfl_xor_sync(0xffffffffu, v, s));
    return v;
}
__device__ __forceinline__ float wsum(float v) {
#pragma unroll
    for (int s = 16; s > 0; s >>= 1) v += __shfl_xor_sync(0xffffffffu, v, s);
    return v;
}

__device__ __forceinline__ float mlp_eval(float c, const float* __restrict__ w1,
                                          const float* __restrict__ b1,
                                          const float* __restrict__ w2, float b2) {
    float acc = b2;
#pragma unroll
    for (int j = 0; j < 32; j++)
        acc += fmaxf(fmaf(c, w1[j], b1[j]), 0.0f) * w2[j];
    return acc;
}

// Warp-per-gene: lane L owns fine bins [4L, 4L+3]. Sums the histogram
// replicas, runs MLP+softmax for all 3 binsets with warp shuffles only,
// writes cconst + combined logits, and re-zeroes g_hist for the next replay.
__global__ void mlp_softmax_kernel(const float* __restrict__ W1,
                                   const float* __restrict__ B1,
                                   const float* __restrict__ W2,
                                   const float* __restrict__ B2, float cconst) {
    __shared__ float w1[3][32], b1[3][32], w2[3][32];
    int t = threadIdx.x;
    if (t < 96) {
        int k = t >> 5, j = t & 31;
        w1[k][j] = W1[t];
        b1[k][j] = B1[t];
        w2[k][j] = W2[t];
    }
    __syncthreads();

    int warp = t >> 5, lane = t & 31;
    int gene = blockIdx.x * 8 + warp;
    int base = gene * NBF + lane * 4;

    int4 cf = make_int4(0, 0, 0, 0);
#pragma unroll
    for (int r = 0; r < REPL; r++) {
        int4 c = *reinterpret_cast<const int4*>(&g_hist[r][base]);
        cf.x += c.x; cf.y += c.y; cf.z += c.z; cf.w += c.w;
        *reinterpret_cast<int4*>(&g_hist[r][base]) = make_int4(0, 0, 0, 0);
    }

    // ---- binset 0 (nb=32): one bin per lane ----
    float c0 = (float)(cf.x + cf.y + cf.z + cf.w) * (32.0f / 20000.0f);
    float h = mlp_eval(c0, w1[0], b1[0], w2[0], B2[0]);
    float m = wmax(h);
    float s = wsum(__expf(h - m));
    float l0 = h - m - logf(s);

    // ---- binset 1 (nb=64): two bins per lane ----
    float ca = (float)(cf.x + cf.y) * (64.0f / 20000.0f);
    float cb = (float)(cf.z + cf.w) * (64.0f / 20000.0f);
    float ha = mlp_eval(ca, w1[1], b1[1], w2[1], B2[1]);
    float hb = mlp_eval(cb, w1[1], b1[1], w2[1], B2[1]);
    float m1 = wmax(fmaxf(ha, hb));
    float s1 = wsum(__expf(ha - m1) + __expf(hb - m1));
    float lse1 = m1 + logf(s1);
    float l1a = ha - lse1, l1b = hb - lse1;

    // ---- binset 2 (nb=128): four bins per lane ----
    const float sc2 = 128.0f / 20000.0f;
    float h0 = mlp_eval((float)cf.x * sc2, w1[2], b1[2], w2[2], B2[2]);
    float h1 = mlp_eval((float)cf.y * sc2, w1[2], b1[2], w2[2], B2[2]);
    float h2 = mlp_eval((float)cf.z * sc2, w1[2], b1[2], w2[2], B2[2]);
    float h3 = mlp_eval((float)cf.w * sc2, w1[2], b1[2], w2[2], B2[2]);
    float m2 = wmax(fmaxf(fmaxf(h0, h1), fmaxf(h2, h3)));
    float s2 = wsum(__expf(h0 - m2) + __expf(h1 - m2) +
                    __expf(h2 - m2) + __expf(h3 - m2));
    float lse2 = m2 + logf(s2);

    float4 r;
    r.x = cconst + l0 + l1a + (h0 - lse2);
    r.y = cconst + l0 + l1a + (h1 - lse2);
    r.z = cconst + l0 + l1b + (h2 - lse2);
    r.w = cconst + l0 + l1b + (h3 - lse2);
    *reinterpret_cast<float4*>(&g_comb[base]) = r;
}

// Final gather: 8 fragments per thread from packed u16 keys (pure gather).
__global__ void frag_kernel(float* __restrict__ out, int n) {
    int i = (blockIdx.x * blockDim.x + threadIdx.x) * 8;
    if (i + 7 < n) {
        uint4 pk = *reinterpret_cast<const uint4*>(g_fkey + i);
        float4 r0, r1;
        r0.x = g_comb[pk.x & 0xffffu];
        r0.y = g_comb[pk.x >> 16];
        r0.z = g_comb[pk.y & 0xffffu];
        r0.w = g_comb[pk.y >> 16];
        r1.x = g_comb[pk.z & 0xffffu];
        r1.y = g_comb[pk.z >> 16];
        r1.z = g_comb[pk.w & 0xffffu];
        r1.w = g_comb[pk.w >> 16];
        *reinterpret_cast<float4*>(out + i) = r0;
        *reinterpret_cast<float4*>(out + i + 4) = r1;
    } else {
        for (; i < n; i++)
            out[i] = g_comb[g_fkey[i]];
    }
}

extern "C" void kernel_launch(void* const* d_in, const int* in_sizes, int n_in,
                              void* d_out, int out_size) {
    const int*   coords = (const int*)d_in[0];   // coordinates        [2M]
    const int*   fgene  = (const int*)d_in[1];   // frag_local_gene_ix [2M]
    const int*   mpos   = (const int*)d_in[2];   // motif_positions    [5M]
    const int*   mgene  = (const int*)d_in[3];   // motif_local_gene_ix[5M]
    // d_in[4..6] = bins0/1/2 (unused: equal-width bins computed in closed form)
    const float* W1 = (const float*)d_in[7];     // (3,1,32)
    const float* B1 = (const float*)d_in[8];     // (3,32)
    const float* W2 = (const float*)d_in[9];     // (3,32,1)
    const float* B2 = (const float*)d_in[10];    // (3,1)

    int nfrag = in_sizes[0];
    int nmot  = in_sizes[2];
    float* out = (float*)d_out;

    // log(32) + log(64) + log(128) - log(20000)
    const float cconst = logf(262144.0f / 20000.0f);

    int nhb = (nmot + 2047) / 2048;   // hist blocks (2048 motifs each)
    int nkb = (nfrag + 2047) / 2048;  // key blocks
    int q   = (nhb + 4) / 5;
    int q2  = (nkb + 1) / 2;
    if (q2 > q) q = q2;
    int grid = 7 * q;

    hist_and_key_kernel<<<grid, 256>>>(mpos, mgene, nmot, coords, fgene, nfrag);
    mlp_softmax_kernel<<<NGENES / 8, 256>>>(W1, B1, W2, B2, cconst);
    frag_kernel<<<(nfrag + 2047) / 2048, 256>>>(out, nfrag);
}

// round 12
// speedup vs baseline: 2.0394x; 2.0394x over previous
#include <cuda_runtime.h>
#include <math.h>

#define NGENES 512
#define NBF 128                         /* fine bins */
#define HTOT (NGENES * NBF)             /* 65536 */
#define REPL 4                          /* histogram replicas */
#define MAXFRAG 2100000
#define NMLPB (NGENES / 8)              /* 64 mlp blocks */

// L2-resident scratch (no allocations allowed -> __device__ globals).
// g_hist is zero-initialized at module load and RE-ZEROED by the mlp phase,
// so every graph replay starts from a clean histogram. g_done/g_exit are
// reset by the last block of mlp_frag_kernel each run.
__device__ int            g_hist[REPL][HTOT];
__device__ float          g_comb[HTOT];       // cconst + L0+L1+L2 combined logits
__device__ unsigned short g_fkey[MAXFRAG];    // per-fragment packed key g*128+bin
__device__ unsigned       g_done;             // mlp blocks completed
__device__ unsigned       g_exit;             // blocks exited (for reset)

// Exact integer reproduction of jnp.searchsorted(interior_bins, x, side='left')
// for equal-width bins: idx = ceil(x*nb/20000) - 1, clamped at 0 via trunc division.
__device__ __forceinline__ int bin_idx128(int x) {
    return (x * NBF - 1) / 20000;
}

// Fused kernel (empirically best config): "hist blocks" (5-of-7) do one
// 32-lane spread RED.ADD per motif into replica (b&3); "key blocks" (2-of-7)
// precompute packed fragment keys on the idle DRAM/ALU pipes.
__global__ void hist_and_key_kernel(const int* __restrict__ mpos,
                                    const int* __restrict__ mgene, int nmot,
                                    const int* __restrict__ coords,
                                    const int* __restrict__ fgene, int nfrag) {
    int b  = blockIdx.x;
    int r7 = b % 7, q = b / 7;

    if (r7 < 2) {
        // ---- fragment key block (2048 fragments) ----
        int kb = q * 2 + r7;
        int i  = kb * 2048 + threadIdx.x * 8;
        if (i + 7 < nfrag) {
            int4 x0 = *reinterpret_cast<const int4*>(coords + i);
            int4 x1 = *reinterpret_cast<const int4*>(coords + i + 4);
            int4 g0 = *reinterpret_cast<const int4*>(fgene + i);
            int4 g1 = *reinterpret_cast<const int4*>(fgene + i + 4);
            uint4 pk;
            pk.x = (unsigned)(g0.x * NBF + bin_idx128(x0.x))
                 | ((unsigned)(g0.y * NBF + bin_idx128(x0.y)) << 16);
            pk.y = (unsigned)(g0.z * NBF + bin_idx128(x0.z))
                 | ((unsigned)(g0.w * NBF + bin_idx128(x0.w)) << 16);
            pk.z = (unsigned)(g1.x * NBF + bin_idx128(x1.x))
                 | ((unsigned)(g1.y * NBF + bin_idx128(x1.y)) << 16);
            pk.w = (unsigned)(g1.z * NBF + bin_idx128(x1.z))
                 | ((unsigned)(g1.w * NBF + bin_idx128(x1.w)) << 16);
            *reinterpret_cast<uint4*>(g_fkey + i) = pk;
        } else if (i < nfrag) {
            for (; i < nfrag; i++)
                g_fkey[i] = (unsigned short)(fgene[i] * NBF + bin_idx128(coords[i]));
        }
    } else {
        // ---- histogram block (2048 motifs, 8 per thread) ----
        int hb = q * 5 + (r7 - 2);
        int i  = hb * 2048 + threadIdx.x * 8;
        int* __restrict__ hist = g_hist[b & 3];
        if (i + 7 < nmot) {
            int4 p0 = *reinterpret_cast<const int4*>(mpos + i);
            int4 p1 = *reinterpret_cast<const int4*>(mpos + i + 4);
            int4 g0 = *reinterpret_cast<const int4*>(mgene + i);
            int4 g1 = *reinterpret_cast<const int4*>(mgene + i + 4);
            atomicAdd(&hist[g0.x * NBF + bin_idx128(p0.x)], 1);
            atomicAdd(&hist[g0.y * NBF + bin_idx128(p0.y)], 1);
            atomicAdd(&hist[g0.z * NBF + bin_idx128(p0.z)], 1);
            atomicAdd(&hist[g0.w * NBF + bin_idx128(p0.w)], 1);
            atomicAdd(&hist[g1.x * NBF + bin_idx128(p1.x)], 1);
            atomicAdd(&hist[g1.y * NBF + bin_idx128(p1.y)], 1);
            atomicAdd(&hist[g1.z * NBF + bin_idx128(p1.z)], 1);
            atomicAdd(&hist[g1.w * NBF + bin_idx128(p1.w)], 1);
        } else if (i < nmot) {
            for (; i < nmot; i++)
                atomicAdd(&hist[mgene[i] * NBF + bin_idx128(mpos[i])], 1);
        }
    }
}

__device__ __forceinline__ float wmax(float v) {
#pragma unroll
    for (int s = 16; s > 0; s >>= 1) v = fmaxf(v, __shfl_xor_sync(0xffffffffu, v, s));
    return v;
}
__device__ __forceinline__ float wsum(float v) {
#pragma unroll
    for (int s = 16; s > 0; s >>= 1) v += __shfl_xor_sync(0xffffffffu, v, s);
    return v;
}

__device__ __forceinline__ float mlp_eval(float c, const float* __restrict__ w1,
                                          const float* __restrict__ b1,
                                          const float* __restrict__ w2, float b2) {
    float acc = b2;
#pragma unroll
    for (int j = 0; j < 32; j++)
        acc += fmaxf(fmaf(c, w1[j], b1[j]), 0.0f) * w2[j];
    return acc;
}

// Merged MLP + gather kernel. Blocks 0..63: warp-per-gene MLP/softmax into
// g_comb (and re-zero g_hist), then signal g_done. ALL blocks gate on
// g_done==NMLPB, then gather their 2048-fragment chunk. Safe: grid (<=1184)
// is fully co-resident at this register/thread footprint, and blocks 0..63
// belong to wave 1, so the gate cannot deadlock. Last block out resets
// g_done/g_exit for the next graph replay.
__global__ void __launch_bounds__(256, 8)
mlp_frag_kernel(const float* __restrict__ W1, const float* __restrict__ B1,
                const float* __restrict__ W2, const float* __restrict__ B2,
                float* __restrict__ out, int nfrag, float cconst) {
    int t = threadIdx.x;

    if (blockIdx.x < NMLPB) {
        // ================= MLP + softmax phase =================
        __shared__ float w1[3][32], b1[3][32], w2[3][32];
        if (t < 96) {
            int k = t >> 5, j = t & 31;
            w1[k][j] = W1[t];
            b1[k][j] = B1[t];
            w2[k][j] = W2[t];
        }
        __syncthreads();

        int warp = t >> 5, lane = t & 31;
        int gene = blockIdx.x * 8 + warp;
        int base = gene * NBF + lane * 4;

        int4 cf = make_int4(0, 0, 0, 0);
#pragma unroll
        for (int r = 0; r < REPL; r++) {
            int4 c = *reinterpret_cast<const int4*>(&g_hist[r][base]);
            cf.x += c.x; cf.y += c.y; cf.z += c.z; cf.w += c.w;
            *reinterpret_cast<int4*>(&g_hist[r][base]) = make_int4(0, 0, 0, 0);
        }

        // binset 0 (nb=32): one bin per lane
        float c0 = (float)(cf.x + cf.y + cf.z + cf.w) * (32.0f / 20000.0f);
        float h = mlp_eval(c0, w1[0], b1[0], w2[0], B2[0]);
        float m = wmax(h);
        float s = wsum(__expf(h - m));
        float l0 = h - m - logf(s);

        // binset 1 (nb=64): two bins per lane
        float ca = (float)(cf.x + cf.y) * (64.0f / 20000.0f);
        float cb = (float)(cf.z + cf.w) * (64.0f / 20000.0f);
        float ha = mlp_eval(ca, w1[1], b1[1], w2[1], B2[1]);
        float hb = mlp_eval(cb, w1[1], b1[1], w2[1], B2[1]);
        float m1 = wmax(fmaxf(ha, hb));
        float s1 = wsum(__expf(ha - m1) + __expf(hb - m1));
        float lse1 = m1 + logf(s1);
        float l1a = ha - lse1, l1b = hb - lse1;

        // binset 2 (nb=128): four bins per lane
        const float sc2 = 128.0f / 20000.0f;
        float h0 = mlp_eval((float)cf.x * sc2, w1[2], b1[2], w2[2], B2[2]);
        float h1 = mlp_eval((float)cf.y * sc2, w1[2], b1[2], w2[2], B2[2]);
        float h2 = mlp_eval((float)cf.z * sc2, w1[2], b1[2], w2[2], B2[2]);
        float h3 = mlp_eval((float)cf.w * sc2, w1[2], b1[2], w2[2], B2[2]);
        float m2 = wmax(fmaxf(fmaxf(h0, h1), fmaxf(h2, h3)));
        float s2 = wsum(__expf(h0 - m2) + __expf(h1 - m2) +
                        __expf(h2 - m2) + __expf(h3 - m2));
        float lse2 = m2 + logf(s2);

        float4 r;
        r.x = cconst + l0 + l1a + (h0 - lse2);
        r.y = cconst + l0 + l1a + (h1 - lse2);
        r.z = cconst + l0 + l1b + (h2 - lse2);
        r.w = cconst + l0 + l1b + (h3 - lse2);
        *reinterpret_cast<float4*>(&g_comb[base]) = r;

        __syncthreads();
        if (t == 0) {
            __threadfence();
            atomicAdd(&g_done, 1u);
        }
    }

    // ================= gate: wait for all mlp blocks =================
    if (t == 0) {
        while (*(volatile unsigned*)&g_done < NMLPB) { }
    }
    __syncthreads();

    // ================= fragment gather (all blocks) =================
    {
        int i = (blockIdx.x * 256 + t) * 8;
        if (i + 7 < nfrag) {
            uint4 pk = *reinterpret_cast<const uint4*>(g_fkey + i);
            float4 r0, r1;
            r0.x = g_comb[pk.x & 0xffffu];
            r0.y = g_comb[pk.x >> 16];
            r0.z = g_comb[pk.y & 0xffffu];
            r0.w = g_comb[pk.y >> 16];
            r1.x = g_comb[pk.z & 0xffffu];
            r1.y = g_comb[pk.z >> 16];
            r1.z = g_comb[pk.w & 0xffffu];
            r1.w = g_comb[pk.w >> 16];
            *reinterpret_cast<float4*>(out + i) = r0;
            *reinterpret_cast<float4*>(out + i + 4) = r1;
        } else {
            for (; i < nfrag; i++)
                out[i] = g_comb[g_fkey[i]];
        }
    }

    // ================= reset for next graph replay =================
    __syncthreads();
    if (t == 0) {
        unsigned e = atomicAdd(&g_exit, 1u);
        if (e == gridDim.x - 1) {
            g_done = 0;
            g_exit = 0;
            __threadfence();
        }
    }
}

extern "C" void kernel_launch(void* const* d_in, const int* in_sizes, int n_in,
                              void* d_out, int out_size) {
    const int*   coords = (const int*)d_in[0];   // coordinates        [2M]
    const int*   fgene  = (const int*)d_in[1];   // frag_local_gene_ix [2M]
    const int*   mpos   = (const int*)d_in[2];   // motif_positions    [5M]
    const int*   mgene  = (const int*)d_in[3];   // motif_local_gene_ix[5M]
    // d_in[4..6] = bins0/1/2 (unused: equal-width bins computed in closed form)
    const float* W1 = (const float*)d_in[7];     // (3,1,32)
    const float* B1 = (const float*)d_in[8];     // (3,32)
    const float* W2 = (const float*)d_in[9];     // (3,32,1)
    const float* B2 = (const float*)d_in[10];    // (3,1)

    int nfrag = in_sizes[0];
    int nmot  = in_sizes[2];
    float* out = (float*)d_out;

    // log(32) + log(64) + log(128) - log(20000)
    const float cconst = logf(262144.0f / 20000.0f);

    int nhb = (nmot + 2047) / 2048;   // hist blocks (8 motifs/thread, 256 thr)
    int nkb = (nfrag + 2047) / 2048;  // key blocks
    int q   = (nhb + 4) / 5;
    int q2  = (nkb + 1) / 2;
    if (q2 > q) q = q2;
    int grid = 7 * q;

    int fgrid = (nfrag + 2047) / 2048;           // 977 for 2M; >= NMLPB
    if (fgrid < NMLPB) fgrid = NMLPB;

    hist_and_key_kernel<<<grid, 256>>>(mpos, mgene, nmot, coords, fgene, nfrag);
    mlp_frag_kernel<<<fgrid, 256>>>(W1, B1, W2, B2, out, nfrag, cconst);
}

// round 13
// speedup vs baseline: 2.2170x; 1.0871x over previous
#include <cuda_runtime.h>
#include <math.h>

#define NGENES 512
#define NBF 128                         /* fine bins */
#define HTOT (NGENES * NBF)             /* 65536 */
#define REPL 4                          /* histogram replicas */
#define MAXFRAG 2100000
#define NMLPB (NGENES / 8)              /* 64 mlp blocks */

// L2-resident scratch (no allocations allowed -> __device__ globals).
// g_hist is zero-initialized at module load and RE-ZEROED by the mlp kernel
// after reading, so every graph replay starts from a clean histogram.
__device__ int            g_hist[REPL][HTOT];
__device__ float          g_comb[HTOT];       // cconst + L0+L1+L2 combined logits
__device__ unsigned short g_fkey[MAXFRAG];    // per-fragment packed key g*128+bin

// Exact integer reproduction of jnp.searchsorted(interior_bins, x, side='left')
// for equal-width bins: idx = ceil(x*nb/20000) - 1, clamped at 0 via trunc division.
__device__ __forceinline__ int bin_idx128(int x) {
    return (x * NBF - 1) / 20000;
}

// Fused kernel (empirically best config): "hist blocks" (5-of-7) do one
// 32-lane spread RED.ADD per motif into replica (b&3); "key blocks" (2-of-7)
// precompute packed fragment keys on the idle DRAM/ALU pipes.
__global__ void hist_and_key_kernel(const int* __restrict__ mpos,
                                    const int* __restrict__ mgene, int nmot,
                                    const int* __restrict__ coords,
                                    const int* __restrict__ fgene, int nfrag) {
    int b  = blockIdx.x;
    int r7 = b % 7, q = b / 7;

    if (r7 < 2) {
        // ---- fragment key block (2048 fragments) ----
        int kb = q * 2 + r7;
        int i  = kb * 2048 + threadIdx.x * 8;
        if (i + 7 < nfrag) {
            int4 x0 = *reinterpret_cast<const int4*>(coords + i);
            int4 x1 = *reinterpret_cast<const int4*>(coords + i + 4);
            int4 g0 = *reinterpret_cast<const int4*>(fgene + i);
            int4 g1 = *reinterpret_cast<const int4*>(fgene + i + 4);
            uint4 pk;
            pk.x = (unsigned)(g0.x * NBF + bin_idx128(x0.x))
                 | ((unsigned)(g0.y * NBF + bin_idx128(x0.y)) << 16);
            pk.y = (unsigned)(g0.z * NBF + bin_idx128(x0.z))
                 | ((unsigned)(g0.w * NBF + bin_idx128(x0.w)) << 16);
            pk.z = (unsigned)(g1.x * NBF + bin_idx128(x1.x))
                 | ((unsigned)(g1.y * NBF + bin_idx128(x1.y)) << 16);
            pk.w = (unsigned)(g1.z * NBF + bin_idx128(x1.z))
                 | ((unsigned)(g1.w * NBF + bin_idx128(x1.w)) << 16);
            *reinterpret_cast<uint4*>(g_fkey + i) = pk;
        } else if (i < nfrag) {
            for (; i < nfrag; i++)
                g_fkey[i] = (unsigned short)(fgene[i] * NBF + bin_idx128(coords[i]));
        }
    } else {
        // ---- histogram block (2048 motifs, 8 per thread) ----
        int hb = q * 5 + (r7 - 2);
        int i  = hb * 2048 + threadIdx.x * 8;
        int* __restrict__ hist = g_hist[b & 3];
        if (i + 7 < nmot) {
            int4 p0 = *reinterpret_cast<const int4*>(mpos + i);
            int4 p1 = *reinterpret_cast<const int4*>(mpos + i + 4);
            int4 g0 = *reinterpret_cast<const int4*>(mgene + i);
            int4 g1 = *reinterpret_cast<const int4*>(mgene + i + 4);
            atomicAdd(&hist[g0.x * NBF + bin_idx128(p0.x)], 1);
            atomicAdd(&hist[g0.y * NBF + bin_idx128(p0.y)], 1);
            atomicAdd(&hist[g0.z * NBF + bin_idx128(p0.z)], 1);
            atomicAdd(&hist[g0.w * NBF + bin_idx128(p0.w)], 1);
            atomicAdd(&hist[g1.x * NBF + bin_idx128(p1.x)], 1);
            atomicAdd(&hist[g1.y * NBF + bin_idx128(p1.y)], 1);
            atomicAdd(&hist[g1.z * NBF + bin_idx128(p1.z)], 1);
            atomicAdd(&hist[g1.w * NBF + bin_idx128(p1.w)], 1);
        } else if (i < nmot) {
            for (; i < nmot; i++)
                atomicAdd(&hist[mgene[i] * NBF + bin_idx128(mpos[i])], 1);
        }
    }
#if __CUDA_ARCH__ >= 900
    cudaTriggerProgrammaticLaunchCompletion();
#endif
}

__device__ __forceinline__ float wmax(float v) {
#pragma unroll
    for (int s = 16; s > 0; s >>= 1) v = fmaxf(v, __shfl_xor_sync(0xffffffffu, v, s));
    return v;
}
__device__ __forceinline__ float wsum(float v) {
#pragma unroll
    for (int s = 16; s > 0; s >>= 1) v += __shfl_xor_sync(0xffffffffu, v, s);
    return v;
}

__device__ __forceinline__ float mlp_eval(float c, const float* __restrict__ w1,
                                          const float* __restrict__ b1,
                                          const float* __restrict__ w2, float b2) {
    float acc = b2;
#pragma unroll
    for (int j = 0; j < 32; j++)
        acc += fmaxf(fmaf(c, w1[j], b1[j]), 0.0f) * w2[j];
    return acc;
}

// Warp-per-gene MLP + softmax. Launched with PDL: loads weights (independent
// of hist output) BEFORE cudaGridDependencySynchronize, then reads g_hist.
__global__ void mlp_softmax_kernel(const float* __restrict__ W1,
                                   const float* __restrict__ B1,
                                   const float* __restrict__ W2,
                                   const float* __restrict__ B2, float cconst) {
    __shared__ float w1[3][32], b1[3][32], w2[3][32];
    int t = threadIdx.x;
    if (t < 96) {
        int k = t >> 5, j = t & 31;
        w1[k][j] = W1[t];
        b1[k][j] = B1[t];
        w2[k][j] = W2[t];
    }
#if __CUDA_ARCH__ >= 900
    cudaGridDependencySynchronize();   // wait for hist_and_key completion
#endif
    __syncthreads();

    int warp = t >> 5, lane = t & 31;
    int gene = blockIdx.x * 8 + warp;
    int base = gene * NBF + lane * 4;

    int4 cf = make_int4(0, 0, 0, 0);
#pragma unroll
    for (int r = 0; r < REPL; r++) {
        int4 c = *reinterpret_cast<const int4*>(&g_hist[r][base]);
        cf.x += c.x; cf.y += c.y; cf.z += c.z; cf.w += c.w;
        *reinterpret_cast<int4*>(&g_hist[r][base]) = make_int4(0, 0, 0, 0);
    }

    // ---- binset 0 (nb=32): one bin per lane ----
    float c0 = (float)(cf.x + cf.y + cf.z + cf.w) * (32.0f / 20000.0f);
    float h = mlp_eval(c0, w1[0], b1[0], w2[0], B2[0]);
    float m = wmax(h);
    float s = wsum(__expf(h - m));
    float l0 = h - m - logf(s);

    // ---- binset 1 (nb=64): two bins per lane ----
    float ca = (float)(cf.x + cf.y) * (64.0f / 20000.0f);
    float cb = (float)(cf.z + cf.w) * (64.0f / 20000.0f);
    float ha = mlp_eval(ca, w1[1], b1[1], w2[1], B2[1]);
    float hb = mlp_eval(cb, w1[1], b1[1], w2[1], B2[1]);
    float m1 = wmax(fmaxf(ha, hb));
    float s1 = wsum(__expf(ha - m1) + __expf(hb - m1));
    float lse1 = m1 + logf(s1);
    float l1a = ha - lse1, l1b = hb - lse1;

    // ---- binset 2 (nb=128): four bins per lane ----
    const float sc2 = 128.0f / 20000.0f;
    float h0 = mlp_eval((float)cf.x * sc2, w1[2], b1[2], w2[2], B2[2]);
    float h1 = mlp_eval((float)cf.y * sc2, w1[2], b1[2], w2[2], B2[2]);
    float h2 = mlp_eval((float)cf.z * sc2, w1[2], b1[2], w2[2], B2[2]);
    float h3 = mlp_eval((float)cf.w * sc2, w1[2], b1[2], w2[2], B2[2]);
    float m2 = wmax(fmaxf(fmaxf(h0, h1), fmaxf(h2, h3)));
    float s2 = wsum(__expf(h0 - m2) + __expf(h1 - m2) +
                    __expf(h2 - m2) + __expf(h3 - m2));
    float lse2 = m2 + logf(s2);

    float4 r;
    r.x = cconst + l0 + l1a + (h0 - lse2);
    r.y = cconst + l0 + l1a + (h1 - lse2);
    r.z = cconst + l0 + l1b + (h2 - lse2);
    r.w = cconst + l0 + l1b + (h3 - lse2);
    *reinterpret_cast<float4*>(&g_comb[base]) = r;
#if __CUDA_ARCH__ >= 900
    cudaTriggerProgrammaticLaunchCompletion();
#endif
}

// Final gather: 8 fragments per thread from packed u16 keys (pure gather).
// PDL: waits on mlp completion (which itself waited on hist, so g_fkey and
// g_comb are both complete after the sync).
__global__ void frag_kernel(float* __restrict__ out, int n) {
#if __CUDA_ARCH__ >= 900
    cudaGridDependencySynchronize();
#endif
    int i = (blockIdx.x * blockDim.x + threadIdx.x) * 8;
    if (i + 7 < n) {
        uint4 pk = *reinterpret_cast<const uint4*>(g_fkey + i);
        float4 r0, r1;
        r0.x = g_comb[pk.x & 0xffffu];
        r0.y = g_comb[pk.x >> 16];
        r0.z = g_comb[pk.y & 0xffffu];
        r0.w = g_comb[pk.y >> 16];
        r1.x = g_comb[pk.z & 0xffffu];
        r1.y = g_comb[pk.z >> 16];
        r1.z = g_comb[pk.w & 0xffffu];
        r1.w = g_comb[pk.w >> 16];
        *reinterpret_cast<float4*>(out + i) = r0;
        *reinterpret_cast<float4*>(out + i + 4) = r1;
    } else {
        for (; i < n; i++)
            out[i] = g_comb[g_fkey[i]];
    }
}

extern "C" void kernel_launch(void* const* d_in, const int* in_sizes, int n_in,
                              void* d_out, int out_size) {
    const int*   coords = (const int*)d_in[0];   // coordinates        [2M]
    const int*   fgene  = (const int*)d_in[1];   // frag_local_gene_ix [2M]
    const int*   mpos   = (const int*)d_in[2];   // motif_positions    [5M]
    const int*   mgene  = (const int*)d_in[3];   // motif_local_gene_ix[5M]
    // d_in[4..6] = bins0/1/2 (unused: equal-width bins computed in closed form)
    const float* W1 = (const float*)d_in[7];     // (3,1,32)
    const float* B1 = (const float*)d_in[8];     // (3,32)
    const float* W2 = (const float*)d_in[9];     // (3,32,1)
    const float* B2 = (const float*)d_in[10];    // (3,1)

    int nfrag = in_sizes[0];
    int nmot  = in_sizes[2];
    float* out = (float*)d_out;

    // log(32) + log(64) + log(128) - log(20000)
    const float cconst = logf(262144.0f / 20000.0f);

    int nhb = (nmot + 2047) / 2048;   // hist blocks (8 motifs/thread, 256 thr)
    int nkb = (nfrag + 2047) / 2048;  // key blocks
    int q   = (nhb + 4) / 5;
    int q2  = (nkb + 1) / 2;
    if (q2 > q) q = q2;
    int grid = 7 * q;

    // Kernel 1: plain launch
    hist_and_key_kernel<<<grid, 256>>>(mpos, mgene, nmot, coords, fgene, nfrag);

    // Kernels 2 & 3: programmatic dependent launches (overlap launch ramps)
    cudaLaunchAttribute attr[1];
    attr[0].id = cudaLaunchAttributeProgrammaticStreamSerialization;
    attr[0].val.programmaticStreamSerializationAllowed = 1;

    {
        cudaLaunchConfig_t cfg = {};
        cfg.gridDim  = dim3(NMLPB, 1, 1);
        cfg.blockDim = dim3(256, 1, 1);
        cfg.attrs = attr;
        cfg.numAttrs = 1;
        cudaLaunchKernelEx(&cfg, mlp_softmax_kernel, W1, B1, W2, B2, cconst);
    }
    {
        cudaLaunchConfig_t cfg = {};
        cfg.gridDim  = dim3((unsigned)((nfrag + 2047) / 2048), 1, 1);
        cfg.blockDim = dim3(256, 1, 1);
        cfg.attrs = attr;
        cfg.numAttrs = 1;
        cudaLaunchKernelEx(&cfg, frag_kernel, out, nfrag);
    }
}